// round 2
// baseline (speedup 1.0000x reference)
#include <cuda_runtime.h>
#include <math.h>

// =====================================================================
// FrFTPool: out = |A · X · B^T| per 128x128 image, where A,B (64x128
// complex) are built on-device from the Candan/Ozaktas FrFT algorithm's
// exact linear-map closed form, with the center crop folded in.
// =====================================================================

#define NBIG 128
#define NSMALL 64
#define NIMG 256          // 8*32
#define XS_ROW 132        // padded row for transposed X in smem (floats)
#define TS_ROW 66         // padded row for T in smem (float2) == 132 floats

// ---------------- device scratch (no allocations allowed) -------------
__device__ float2 d_M1[NBIG * NBIG];
__device__ float2 d_M2[NBIG * NBIG];
__device__ float2 d_M3[NSMALL * NSMALL];
__device__ float2 d_M4[NSMALL * NSMALL];
__device__ float2 d_At[NBIG * NSMALL];   // At[h][i] = A[i][h]
__device__ float2 d_Bt[NBIG * NSMALL];   // Bt[k][j] = B[j][k]

__device__ double2 d_Ktab[4][4 * NBIG];  // up to 4N-3 = 509 entries
__device__ double2 d_Ctab[4][2 * NBIG];  // up to 2N-1 = 255 entries
__device__ double2 d_pref[4];
__device__ int     d_flip[4];

// ---------------- 1) chirp tables (double precision) ------------------
// matrix m: 0 -> order1 @N=128 (W fwd), 1 -> order2 @N=128 (H fwd),
//           2 -> -order1 @N=64 (W inv), 3 -> -order2 @N=64 (H inv)
__global__ void build_tables(const float* __restrict__ order1,
                             const float* __restrict__ order2) {
    int m = blockIdx.x;
    int N = (m < 2) ? NBIG : NSMALL;
    float ap = ((m == 0) || (m == 2)) ? order1[0] : order2[0];
    if (m >= 2) ap = -ap;

    double a = fmod((double)ap, 4.0);
    if (a < 0.0) a += 4.0;
    int flip = 0;
    if (a > 2.0) { flip = 1; a -= 2.0; }
    // (orders 1.25 / -1.25 reduce to 1.25 / 0.75 -> core path only)

    double alpha = a * M_PI * 0.5;
    double tana2 = tan(alpha * 0.5);
    double sina  = sin(alpha);
    double c     = M_PI / (4.0 * (double)N * sina);
    double kch   = (M_PI / (double)N) * tana2 * 0.25;

    int t = threadIdx.x;
    for (int i = t; i < 4 * N - 3; i += blockDim.x) {
        double mm = (double)(i - (2 * N - 2));
        double th = c * mm * mm;
        double s, co; sincos(th, &s, &co);
        d_Ktab[m][i] = make_double2(co, s);
    }
    for (int p = t; p < 2 * N - 1; p += blockDim.x) {
        double n = (double)(p - (N - 1));
        double th = -kch * n * n;
        double s, co; sincos(th, &s, &co);
        d_Ctab[m][p] = make_double2(co, s);
    }
    if (t == 0) {
        double ph = -(1.0 - a) * M_PI * 0.25;
        double s, co; sincos(ph, &s, &co);
        double sc = sqrt(c / M_PI);
        d_pref[m] = make_double2(co * sc, s * sc);
        d_flip[m] = flip;
    }
}

// ---------------- 2) FrFT matrices from tables ------------------------
// M[j,k] = pref * C[2j] * ( K[2(j-kk)]*C[2kk]
//            + sum_t K[2j-2t-1]*C[2t+1]*sinc((2t+1-2kk)/2) ),  kk = flip? N-1-k : k
__global__ void build_matrix() {
    int m = blockIdx.y;
    int N = (m < 2) ? NBIG : NSMALL;
    int j = blockIdx.x;
    if (j >= N) return;

    __shared__ float2 Ks[4 * NBIG];  // 512
    __shared__ float2 Cs[2 * NBIG];  // 256
    for (int i = threadIdx.x; i < 4 * N - 3; i += blockDim.x) {
        double2 v = d_Ktab[m][i];
        Ks[i] = make_float2((float)v.x, (float)v.y);
    }
    for (int i = threadIdx.x; i < 2 * N - 1; i += blockDim.x) {
        double2 v = d_Ctab[m][i];
        Cs[i] = make_float2((float)v.x, (float)v.y);
    }
    __syncthreads();

    int k = threadIdx.x;
    if (k >= N) return;

    int flip = d_flip[m];
    int kk = flip ? (N - 1 - k) : k;
    int off = 2 * N - 2;

    // even-p term (only t == kk survives: sinc(int) = delta)
    float2 Ke = Ks[2 * (j - kk) + off];
    float2 Ce = Cs[2 * kk];
    float sr = Ke.x * Ce.x - Ke.y * Ce.y;
    float si = Ke.x * Ce.y + Ke.y * Ce.x;

    const float inv_pi = 0.31830988618379067f;
    for (int t = 0; t < N - 1; t++) {
        int p = 2 * t + 1;
        int d = p - 2 * kk;           // always odd
        int ad = (d < 0) ? -d : d;
        float sv = (((ad >> 1) & 1) ? -2.0f : 2.0f) * inv_pi / (float)ad;
        float2 K = Ks[2 * j - p + off];
        float2 C = Cs[p];
        float kr = K.x * C.x - K.y * C.y;
        float ki = K.x * C.y + K.y * C.x;
        sr += kr * sv;
        si += ki * sv;
    }

    double2 pr = d_pref[m];
    float2 Cj = Cs[2 * j];
    float pcr = (float)pr.x * Cj.x - (float)pr.y * Cj.y;
    float pci = (float)pr.x * Cj.y + (float)pr.y * Cj.x;
    float2 outv;
    outv.x = pcr * sr - pci * si;
    outv.y = pcr * si + pci * sr;

    float2* M = (m == 0) ? d_M1 : (m == 1) ? d_M2 : (m == 2) ? d_M3 : d_M4;
    M[j * N + k] = outv;
}

// ---------------- 3) fold crop into combined matrices -----------------
// A[i,h] = sum_p M4[i,p] * M2[32+p, h]   -> stored transposed At[h][i]
// B[j,k] = sum_q M3[j,q] * M1[32+q, k]   -> stored transposed Bt[k][j]
__global__ void combine() {
    int i = blockIdx.x;          // 0..63 output row of A/B
    int h = threadIdx.x;         // 0..127 input column
    const float2* L = blockIdx.y ? d_M3 : d_M4;   // 64x64
    const float2* R = blockIdx.y ? d_M1 : d_M2;   // 128x128
    float ar = 0.f, ai = 0.f;
    for (int p = 0; p < NSMALL; p++) {
        float2 l = L[i * NSMALL + p];
        float2 r = R[(32 + p) * NBIG + h];
        ar += l.x * r.x - l.y * r.y;
        ai += l.x * r.y + l.y * r.x;
    }
    float2* T = blockIdx.y ? d_Bt : d_At;
    T[h * NSMALL + i] = make_float2(ar, ai);
}

// ---------------- 4) main fused kernel: per-image |A·X·B^T| -----------
// block = 256 threads, one image per block.
// GEMM1: T[p,j] = sum_k X[p,k]*B[j,k]   (X real)   p<128, j<64
// GEMM2: O[i,j] = | sum_p A[i,p]*T[p,j] |          i<64,  j<64
#define SMEM_BYTES (NBIG * XS_ROW * 4 + 16 * NSMALL * 8)  // 67584 + 8192

__global__ __launch_bounds__(256, 2)
void frft_pool_main(const float* __restrict__ x, float* __restrict__ out) {
    extern __shared__ float smem[];
    float*  Xs   = smem;                                // [128][132] floats
    float2* Tile = (float2*)(smem + NBIG * XS_ROW);     // [16][64] float2

    int tid = threadIdx.x;
    int l = tid & 31;        // lane
    int w = tid >> 5;        // warp 0..7
    int img = blockIdx.x;

    // --- load X transposed into smem: Xs[k][p] = X[p][k] ---
    const float4* xg4 = (const float4*)(x + (size_t)img * (NBIG * NBIG));
    #pragma unroll
    for (int i = 0; i < 16; i++) {
        int idx4 = tid + i * 256;
        float4 v = xg4[idx4];
        int r = idx4 >> 5;            // row p
        int c = (idx4 & 31) << 2;     // col k base
        Xs[(c + 0) * XS_ROW + r] = v.x;
        Xs[(c + 1) * XS_ROW + r] = v.y;
        Xs[(c + 2) * XS_ROW + r] = v.z;
        Xs[(c + 3) * XS_ROW + r] = v.w;
    }

    // thread computes T[4l..4l+3][8w..8w+7]
    float accr[4][8], acci[4][8];
    #pragma unroll
    for (int pp = 0; pp < 4; pp++)
        #pragma unroll
        for (int jj = 0; jj < 8; jj++) { accr[pp][jj] = 0.f; acci[pp][jj] = 0.f; }

    for (int k0 = 0; k0 < NBIG; k0 += 16) {
        __syncthreads();
        #pragma unroll
        for (int i = 0; i < 4; i++) {
            int idx = tid + i * 256;                 // idx = kt*64 + j
            Tile[idx] = d_Bt[k0 * NSMALL + idx];
        }
        __syncthreads();
        #pragma unroll
        for (int kt = 0; kt < 16; kt++) {
            int k = k0 + kt;
            float4 xv = *(const float4*)&Xs[k * XS_ROW + 4 * l];
            float2 b[8];
            #pragma unroll
            for (int jj = 0; jj < 8; jj++) b[jj] = Tile[kt * NSMALL + 8 * w + jj];
            #pragma unroll
            for (int pp = 0; pp < 4; pp++) {
                float xs = (pp == 0) ? xv.x : (pp == 1) ? xv.y : (pp == 2) ? xv.z : xv.w;
                #pragma unroll
                for (int jj = 0; jj < 8; jj++) {
                    accr[pp][jj] = fmaf(xs, b[jj].x, accr[pp][jj]);
                    acci[pp][jj] = fmaf(xs, b[jj].y, acci[pp][jj]);
                }
            }
        }
    }

    // --- write T into smem (reusing Xs region): Ts[p][j], row pitch 66 ---
    __syncthreads();
    float2* Ts = (float2*)smem;
    #pragma unroll
    for (int pp = 0; pp < 4; pp++)
        #pragma unroll
        for (int jj = 0; jj < 8; jj++)
            Ts[(4 * l + pp) * TS_ROW + 8 * w + jj] =
                make_float2(accr[pp][jj], acci[pp][jj]);

    // thread computes O[{l, l+32}][8w..8w+7]
    float or_[2][8], oi_[2][8];
    #pragma unroll
    for (int ii = 0; ii < 2; ii++)
        #pragma unroll
        for (int jj = 0; jj < 8; jj++) { or_[ii][jj] = 0.f; oi_[ii][jj] = 0.f; }

    for (int p0 = 0; p0 < NBIG; p0 += 16) {
        __syncthreads();
        #pragma unroll
        for (int i = 0; i < 4; i++) {
            int idx = tid + i * 256;                 // idx = pt*64 + i
            Tile[idx] = d_At[p0 * NSMALL + idx];
        }
        __syncthreads();
        #pragma unroll
        for (int pt = 0; pt < 16; pt++) {
            int p = p0 + pt;
            float2 a0 = Tile[pt * NSMALL + l];
            float2 a1 = Tile[pt * NSMALL + l + 32];
            float2 t8[8];
            #pragma unroll
            for (int jj = 0; jj < 8; jj++) t8[jj] = Ts[p * TS_ROW + 8 * w + jj];
            #pragma unroll
            for (int jj = 0; jj < 8; jj++) {
                or_[0][jj] = fmaf(a0.x, t8[jj].x, or_[0][jj]);
                or_[0][jj] = fmaf(-a0.y, t8[jj].y, or_[0][jj]);
                oi_[0][jj] = fmaf(a0.x, t8[jj].y, oi_[0][jj]);
                oi_[0][jj] = fmaf(a0.y, t8[jj].x, oi_[0][jj]);
                or_[1][jj] = fmaf(a1.x, t8[jj].x, or_[1][jj]);
                or_[1][jj] = fmaf(-a1.y, t8[jj].y, or_[1][jj]);
                oi_[1][jj] = fmaf(a1.x, t8[jj].y, oi_[1][jj]);
                oi_[1][jj] = fmaf(a1.y, t8[jj].x, oi_[1][jj]);
            }
        }
    }

    float* og = out + (size_t)img * (NSMALL * NSMALL);
    #pragma unroll
    for (int ii = 0; ii < 2; ii++) {
        int i = l + 32 * ii;
        float4 v0, v1;
        v0.x = sqrtf(or_[ii][0] * or_[ii][0] + oi_[ii][0] * oi_[ii][0]);
        v0.y = sqrtf(or_[ii][1] * or_[ii][1] + oi_[ii][1] * oi_[ii][1]);
        v0.z = sqrtf(or_[ii][2] * or_[ii][2] + oi_[ii][2] * oi_[ii][2]);
        v0.w = sqrtf(or_[ii][3] * or_[ii][3] + oi_[ii][3] * oi_[ii][3]);
        v1.x = sqrtf(or_[ii][4] * or_[ii][4] + oi_[ii][4] * oi_[ii][4]);
        v1.y = sqrtf(or_[ii][5] * or_[ii][5] + oi_[ii][5] * oi_[ii][5]);
        v1.z = sqrtf(or_[ii][6] * or_[ii][6] + oi_[ii][6] * oi_[ii][6]);
        v1.w = sqrtf(or_[ii][7] * or_[ii][7] + oi_[ii][7] * oi_[ii][7]);
        *(float4*)&og[i * NSMALL + 8 * w]     = v0;
        *(float4*)&og[i * NSMALL + 8 * w + 4] = v1;
    }
}

// ---------------------------------------------------------------------
extern "C" void kernel_launch(void* const* d_in, const int* in_sizes, int n_in,
                              void* d_out, int out_size) {
    const float* x  = (const float*)d_in[0];
    const float* o1 = (const float*)d_in[1];
    const float* o2 = (const float*)d_in[2];
    float* out = (float*)d_out;

    build_tables<<<4, 512>>>(o1, o2);
    build_matrix<<<dim3(NBIG, 4), 128>>>();
    combine<<<dim3(NSMALL, 2), 128>>>();

    cudaFuncSetAttribute(frft_pool_main,
                         cudaFuncAttributeMaxDynamicSharedMemorySize, SMEM_BYTES);
    frft_pool_main<<<NIMG, 256, SMEM_BYTES>>>(x, out);
}